// round 6
// baseline (speedup 1.0000x reference)
#include <cuda_runtime.h>

#define RAD_N 5
#define AZI_N 30
#define ELE_N 15
#define NBINS (RAD_N * AZI_N * ELE_N)   // 2250
#define BPB   32                        // blocks per batch
#define TPB   256

__global__ void zero_kernel(float* __restrict__ out, int n) {
    int i = blockIdx.x * blockDim.x + threadIdx.x;
    if (i < n) out[i] = 0.0f;
}

__global__ __launch_bounds__(TPB)
void vox_kernel(const float* __restrict__ pts, float* __restrict__ out, int npts_per_batch) {
    __shared__ float hist[NBINS];
    for (int i = threadIdx.x; i < NBINS; i += TPB) hist[i] = 0.0f;
    __syncthreads();

    const int   batch  = blockIdx.y;
    const int   chunk  = blockIdx.x;
    const float TWO_PI = 6.28318530717958647692f;
    const float PIF    = 3.14159265358979323846f;
    const float tr = 2.0f / RAD_N;          // 0.4
    const float sr = tr * 0.5f;             // 0.2
    const float ta = TWO_PI / AZI_N;
    const float te = PIF / ELE_N;
    const float se = te * 0.5f;
    const float inv_tr = 1.0f / tr;
    const float inv_ta = 1.0f / ta;
    const float inv_te = 1.0f / te;

    const float* __restrict__ bpts = pts + (long)batch * npts_per_batch * 3;

    for (int p = chunk * TPB + threadIdx.x; p < npts_per_batch; p += BPB * TPB) {
        const int gi = p * 3;
        float x = bpts[gi + 0];
        float y = bpts[gi + 1];
        float z = bpts[gi + 2];

        float r = sqrtf(fmaf(x, x, fmaf(y, y, z * z)));
        if (r > 2.0f) continue;   // wr forced to 0 for both bins -> contribution is 0

        float azi = atan2f(y, x);
        if (azi < 0.0f) azi += TWO_PI;
        float ele = acosf(fminf(fmaxf(z / fmaxf(r, 1e-12f), -1.0f), 1.0f));

        // ---- radial: two nearest with boundary half-bin fixups ----
        float rd1 = 1e30f, rd2 = 1e30f; int ri1 = 0, ri2 = 0;
        {
            const bool low  = (r < sr);
            const bool high = (r > 2.0f - sr);   // r <= 2 guaranteed above
            #pragma unroll
            for (int j = 0; j < RAD_N; j++) {
                float d = fabsf(r - (j + 0.5f) * tr);
                if (low) {
                    if (d <= sr) d = 0.0f;
                    else if (d > tr && d <= tr + sr) d = tr;
                } else if (high) {
                    if (d > tr && d <= tr + sr) d = tr;
                }
                if (d < rd1) { rd2 = rd1; ri2 = ri1; rd1 = d; ri1 = j; }
                else if (d < rd2) { rd2 = d; ri2 = j; }
            }
        }
        const float wr0 = 1.0f - rd1 * inv_tr;
        const float wr1 = 1.0f - rd2 * inv_tr;

        // ---- azimuth: circular distance, two nearest ----
        float ad1 = 1e30f, ad2 = 1e30f; int ai1 = 0, ai2 = 0;
        #pragma unroll
        for (int j = 0; j < AZI_N; j++) {
            float d = fabsf(azi - (j + 0.5f) * ta);
            d = fminf(d, TWO_PI - d);
            if (d < ad1) { ad2 = ad1; ai2 = ai1; ad1 = d; ai1 = j; }
            else if (d < ad2) { ad2 = d; ai2 = j; }
        }
        const float wa0 = 1.0f - ad1 * inv_ta;
        const float wa1 = 1.0f - ad2 * inv_ta;

        // ---- elevation: two nearest with boundary fixups on both ends ----
        float ed1 = 1e30f, ed2 = 1e30f; int ei1 = 0, ei2 = 0;
        {
            const bool lo = (ele < se);
            const bool hi = (ele > PIF - se);    // acosf range is [0, pi]
            #pragma unroll
            for (int j = 0; j < ELE_N; j++) {
                float d = fabsf(ele - (j + 0.5f) * te);
                if (lo) {
                    if (d <= se) d = 0.0f;
                    else if (d > te && d <= te + se) d = te;
                } else if (hi) {
                    if (d <= 0.75f * te) d = 0.0f;
                    else if (d > te && d <= te + se) d = te;
                }
                if (d < ed1) { ed2 = ed1; ei2 = ei1; ed1 = d; ei1 = j; }
                else if (d < ed2) { ed2 = d; ei2 = j; }
            }
        }
        const float we0 = 1.0f - ed1 * inv_te;
        const float we1 = 1.0f - ed2 * inv_te;

        // ---- 8 trilinear scatter-adds into the shared histogram ----
        const int b00 = (ri1 * AZI_N + ai1) * ELE_N;
        const int b01 = (ri1 * AZI_N + ai2) * ELE_N;
        const int b10 = (ri2 * AZI_N + ai1) * ELE_N;
        const int b11 = (ri2 * AZI_N + ai2) * ELE_N;
        const float w00 = wr0 * wa0;
        const float w01 = wr0 * wa1;
        const float w10 = wr1 * wa0;
        const float w11 = wr1 * wa1;

        atomicAdd(&hist[b00 + ei1], w00 * we0);
        atomicAdd(&hist[b00 + ei2], w00 * we1);
        atomicAdd(&hist[b01 + ei1], w01 * we0);
        atomicAdd(&hist[b01 + ei2], w01 * we1);
        atomicAdd(&hist[b10 + ei1], w10 * we0);
        atomicAdd(&hist[b10 + ei2], w10 * we1);
        atomicAdd(&hist[b11 + ei1], w11 * we0);
        atomicAdd(&hist[b11 + ei2], w11 * we1);
    }

    __syncthreads();

    // ---- flush shared histogram into the global per-batch histogram ----
    float* __restrict__ ob = out + batch * NBINS;
    for (int i = threadIdx.x; i < NBINS; i += TPB) {
        float v = hist[i];
        if (v != 0.0f) atomicAdd(&ob[i], v);
    }
}

extern "C" void kernel_launch(void* const* d_in, const int* in_sizes, int n_in,
                              void* d_out, int out_size) {
    const float* pts = (const float*)d_in[0];
    float* out = (float*)d_out;

    const int batches = out_size / NBINS;                 // 16
    const int npts    = in_sizes[0] / (3 * batches);      // 65536

    zero_kernel<<<(out_size + 255) / 256, 256>>>(out, out_size);

    dim3 grid(BPB, batches);                              // 512 CTAs
    vox_kernel<<<grid, TPB>>>(pts, out, npts);
}

// round 7
// speedup vs baseline: 2.0587x; 2.0587x over previous
#include <cuda_runtime.h>

#define RAD_N 5
#define AZI_N 30
#define ELE_N 15
#define NBINS (RAD_N * AZI_N * ELE_N)   // 2250
#define BPB   32                        // blocks per batch
#define TPB   256

__global__ void zero_kernel(float* __restrict__ out, int n) {
    int i = blockIdx.x * blockDim.x + threadIdx.x;
    if (i < n) out[i] = 0.0f;
}

// Analytic two-nearest-bin for uniform bins with centers (j+0.5)*step.
// u = value/step. Interior: w1 = 1-|f-0.5|, w2 = |f-0.5|, j2 = j1 +/- 1.
// Out-of-range j2 is fixed up per-axis by the caller (reference boundary rules).
__device__ __forceinline__ void axis2(float u, int N,
                                      int& j1, int& j2, float& w1, float& w2) {
    int j = (int)u;                 // u >= 0 always
    if (j > N - 1) j = N - 1;       // u == N edge (and float rounding)
    float f = u - (float)j;
    j1 = j;
    if (f < 0.5f) { j2 = j - 1; w1 = 0.5f + f; w2 = 0.5f - f; }
    else          { j2 = j + 1; w1 = 1.5f - f; w2 = f - 0.5f; }
}

__global__ __launch_bounds__(TPB)
void vox_kernel(const float* __restrict__ pts, float* __restrict__ out, int npts_per_batch) {
    __shared__ float hist[NBINS];
    for (int i = threadIdx.x; i < NBINS; i += TPB) hist[i] = 0.0f;
    __syncthreads();

    const int   batch  = blockIdx.y;
    const int   chunk  = blockIdx.x;
    const float TWO_PI = 6.28318530717958647692f;
    const float PIF    = 3.14159265358979323846f;
    const float inv_tr = (float)RAD_N / 2.0f;       // 1/tr
    const float inv_ta = (float)AZI_N / TWO_PI;     // 1/ta
    const float inv_te = (float)ELE_N / PIF;        // 1/te

    const float* __restrict__ bpts = pts + (long)batch * npts_per_batch * 3;

    for (int p = chunk * TPB + threadIdx.x; p < npts_per_batch; p += BPB * TPB) {
        const int gi = p * 3;
        float x = bpts[gi + 0];
        float y = bpts[gi + 1];
        float z = bpts[gi + 2];

        float r = sqrtf(fmaf(x, x, fmaf(y, y, z * z)));
        if (r > 2.0f) continue;   // both radial weights forced to 0 by reference

        float azi = atan2f(y, x);
        if (azi < 0.0f) azi += TWO_PI;
        float c = z / fmaxf(r, 1e-12f);
        float ele = acosf(fminf(fmaxf(c, -1.0f), 1.0f));

        // ---- radial ----
        int ri1, ri2; float wr0, wr1;
        axis2(r * inv_tr, RAD_N, ri1, ri2, wr0, wr1);
        if (ri2 < 0)               { wr0 = 1.0f; wr1 = 0.0f; ri2 = 1; }          // r < sr
        else if (ri2 > RAD_N - 1)  { wr1 = 0.0f; ri2 = RAD_N - 2; }              // r > 2 - sr

        // ---- azimuth (circular) ----
        int ai1, ai2; float wa0, wa1;
        axis2(azi * inv_ta, AZI_N, ai1, ai2, wa0, wa1);
        if (ai2 < 0) ai2 = AZI_N - 1;
        else if (ai2 > AZI_N - 1) ai2 = 0;

        // ---- elevation ----
        int ei1, ei2; float we0, we1;
        axis2(ele * inv_te, ELE_N, ei1, ei2, we0, we1);
        if (ei2 < 0)               { we0 = 1.0f; we1 = 0.0f; ei2 = 1; }          // ele < se
        else if (ei2 > ELE_N - 1)  { we0 = 1.0f; we1 = 0.0f; ei2 = ELE_N - 2; }  // ele > pi - se

        // ---- 8 trilinear scatter-adds into the shared histogram ----
        const int b00 = (ri1 * AZI_N + ai1) * ELE_N;
        const int b01 = (ri1 * AZI_N + ai2) * ELE_N;
        const int b10 = (ri2 * AZI_N + ai1) * ELE_N;
        const int b11 = (ri2 * AZI_N + ai2) * ELE_N;
        const float w00 = wr0 * wa0;
        const float w01 = wr0 * wa1;
        const float w10 = wr1 * wa0;
        const float w11 = wr1 * wa1;

        atomicAdd(&hist[b00 + ei1], w00 * we0);
        atomicAdd(&hist[b00 + ei2], w00 * we1);
        atomicAdd(&hist[b01 + ei1], w01 * we0);
        atomicAdd(&hist[b01 + ei2], w01 * we1);
        atomicAdd(&hist[b10 + ei1], w10 * we0);
        atomicAdd(&hist[b10 + ei2], w10 * we1);
        atomicAdd(&hist[b11 + ei1], w11 * we0);
        atomicAdd(&hist[b11 + ei2], w11 * we1);
    }

    __syncthreads();

    // ---- flush shared histogram into the global per-batch histogram ----
    float* __restrict__ ob = out + batch * NBINS;
    for (int i = threadIdx.x; i < NBINS; i += TPB) {
        float v = hist[i];
        if (v != 0.0f) atomicAdd(&ob[i], v);
    }
}

extern "C" void kernel_launch(void* const* d_in, const int* in_sizes, int n_in,
                              void* d_out, int out_size) {
    const float* pts = (const float*)d_in[0];
    float* out = (float*)d_out;

    const int batches = out_size / NBINS;                 // 16
    const int npts    = in_sizes[0] / (3 * batches);      // 65536

    zero_kernel<<<(out_size + 255) / 256, 256>>>(out, out_size);

    dim3 grid(BPB, batches);                              // 512 CTAs
    vox_kernel<<<grid, TPB>>>(pts, out, npts);
}